// round 3
// baseline (speedup 1.0000x reference)
#include <cuda_runtime.h>
#include <math.h>
#include <stdint.h>

#define NPOS 16384          // H*W
#define NB   16             // batch
#define NCH  128            // C == hidden
#define NCHUNK 32           // context n-chunks (512 each)

// ---------------- device scratch (allocation-free rule: __device__ globals) ----
__device__ float g_q[NB * NCH * NPOS];           // softmaxed*scale q  [b][h*32+d][n]
__device__ float g_k[NB * NCH * NPOS];           // raw k             [b][h*32+d][n]
__device__ float g_v[NB * NCH * NPOS];           // raw v             [b][h*32+e][n]
__device__ float g_part[NB * 4 * NCHUNK * 1056]; // per (b,h,chunk): 1024 ctx + 32 sumexp
__device__ float g_W2T[NB * NCH * NCH];          // fused weight, [b][ch=h*32+d][c]

// packed f32x2 helpers ---------------------------------------------------------
__device__ __forceinline__ void ffma2(uint64_t& acc, uint64_t a, uint64_t b) {
    asm("fma.rn.f32x2 %0, %1, %2, %0;" : "+l"(acc) : "l"(a), "l"(b));
}
__device__ __forceinline__ uint64_t pack_dup(float w) {
    uint64_t r;
    asm("mov.b64 %0, {%1, %1};" : "=l"(r) : "f"(w));
    return r;
}
__device__ __forceinline__ float2 unpk(uint64_t v) {
    float2 f;
    asm("mov.b64 {%0, %1}, %2;" : "=f"(f.x), "=f"(f.y) : "l"(v));
    return f;
}

// =============================================================================
// K1: qkv = w_qkv @ x.  Per block: 128 positions x all 384 out-ch (3 chunks of
// 128).  8x8 register tile per thread via fma.rn.f32x2.
// smem: xs[128][128] | ws[128][132] | qb[128][132] = 200,704 B
// =============================================================================
__global__ __launch_bounds__(256, 1)
void k_qkv(const float* __restrict__ x, const float* __restrict__ w_qkv)
{
    extern __shared__ float sm[];
    float* xs = sm;               // [c][p]   stride 128
    float* ws = sm + 16384;       // [c][o]   stride 132 (padded)
    float* qb = ws + 16896;       // [ch][p]  stride 132 (padded)

    const int b   = blockIdx.x >> 7;
    const int n0  = (blockIdx.x & 127) << 7;
    const int tid = threadIdx.x;

    const float* xb = x + (size_t)b * NCH * NPOS + n0;

#pragma unroll
    for (int i = 0; i < 16; i++) {
        int lin = tid + i * 256;          // 4096 float4
        int c = lin >> 5, pv = lin & 31;
        ((float4*)xs)[c * 32 + pv] = ((const float4*)(xb + (size_t)c * NPOS))[pv];
    }

    const int to = tid >> 4, tp = tid & 15;
    const int o0 = to * 8,   p0 = tp * 8;

    for (int chunk = 0; chunk < 3; chunk++) {
        __syncthreads();
#pragma unroll
        for (int i = 0; i < 64; i++) {
            int lin = tid + i * 256;      // 16384
            int o = lin >> 7, c = lin & 127;
            ws[c * 132 + o] = w_qkv[(chunk * 128 + o) * NCH + c];
        }
        __syncthreads();

        uint64_t acc2[8][4];
#pragma unroll
        for (int i = 0; i < 8; i++)
#pragma unroll
            for (int j = 0; j < 4; j++) acc2[i][j] = 0ull;

#pragma unroll 2
        for (int c = 0; c < 128; c++) {
            const ulonglong2 xa = *(const ulonglong2*)&xs[c * 128 + p0];
            const ulonglong2 xc = *(const ulonglong2*)&xs[c * 128 + p0 + 4];
            const uint64_t xp[4] = {xa.x, xa.y, xc.x, xc.y};
            const float4 w0 = *(const float4*)&ws[c * 132 + o0];
            const float4 w1 = *(const float4*)&ws[c * 132 + o0 + 4];
            const float wv[8] = {w0.x, w0.y, w0.z, w0.w, w1.x, w1.y, w1.z, w1.w};
#pragma unroll
            for (int i = 0; i < 8; i++) {
                const uint64_t wd = pack_dup(wv[i]);
#pragma unroll
                for (int j = 0; j < 4; j++) ffma2(acc2[i][j], wd, xp[j]);
            }
        }

        if (chunk == 0) {                 // q -> smem for softmax
#pragma unroll
            for (int i = 0; i < 8; i++) {
                float2 f0 = unpk(acc2[i][0]), f1 = unpk(acc2[i][1]);
                float2 f2 = unpk(acc2[i][2]), f3 = unpk(acc2[i][3]);
                float* r = &qb[(o0 + i) * 132 + p0];
                *(float4*)(r)     = make_float4(f0.x, f0.y, f1.x, f1.y);
                *(float4*)(r + 4) = make_float4(f2.x, f2.y, f3.x, f3.y);
            }
        } else {
            float* gdst = (chunk == 1) ? g_k : g_v;
            float* dst = gdst + ((size_t)b * NCH + o0) * NPOS + n0 + p0;
#pragma unroll
            for (int i = 0; i < 8; i++) {
                float2 f0 = unpk(acc2[i][0]), f1 = unpk(acc2[i][1]);
                float2 f2 = unpk(acc2[i][2]), f3 = unpk(acc2[i][3]);
                *(float4*)(dst + (size_t)i * NPOS)     = make_float4(f0.x, f0.y, f1.x, f1.y);
                *(float4*)(dst + (size_t)i * NPOS + 4) = make_float4(f2.x, f2.y, f3.x, f3.y);
            }
        }
    }
    __syncthreads();

    // q softmax over d (32) per (h, p), then * DIM_HEAD^-0.5
    const float scale = 0.17677669529663687f; // 32^-0.5
#pragma unroll
    for (int it = 0; it < 2; it++) {
        int item = tid + it * 256;        // 512 = 4 heads * 128 p
        int h = item >> 7, p = item & 127;
        float m = -1e30f;
#pragma unroll
        for (int d = 0; d < 32; d++) m = fmaxf(m, qb[(h * 32 + d) * 132 + p]);
        float s = 0.f;
#pragma unroll
        for (int d = 0; d < 32; d++) {
            float e = __expf(qb[(h * 32 + d) * 132 + p] - m);
            qb[(h * 32 + d) * 132 + p] = e;
            s += e;
        }
        const float inv = scale / s;
        float* dst = g_q + ((size_t)b * NCH + h * 32) * NPOS + n0 + p;
#pragma unroll
        for (int d = 0; d < 32; d++)
            dst[(size_t)d * NPOS] = qb[(h * 32 + d) * 132 + p] * inv;
    }
}

// =============================================================================
// K2a: per (b,h,chunk of 512 n): partial ctx[d][e] = sum exp(k[d,n]) v[e,n]
//      plus partial sumexp per d.  smem: ekT[512][36] | vT[512][36] = 147,456 B
// =============================================================================
__global__ __launch_bounds__(256, 1)
void k_ctx_part()
{
    extern __shared__ float sm[];
    float* ekT = sm;            // [nn][d] stride 36
    float* vT  = sm + 18432;

    const int chunk = blockIdx.x & 31;
    const int bh    = blockIdx.x >> 5;   // b*4 + h
    const int tid   = threadIdx.x;
    const size_t base = (size_t)bh * 32 * NPOS + (size_t)chunk * 512;

    for (int i = 0; i < 64; i++) {
        int lin = tid + i * 256;         // 16384 = 32 d x 512 nn
        int d = lin >> 9, nn = lin & 511;
        ekT[nn * 36 + d] = __expf(g_k[base + (size_t)d * NPOS + nn]);
        vT [nn * 36 + d] =        g_v[base + (size_t)d * NPOS + nn];
    }
    __syncthreads();

    const int g  = tid >> 6;             // 4 groups, each owns 128 nn
    const int t  = tid & 63;
    const int td = t >> 3, te = t & 7;
    const int d0 = td * 4, e0 = te * 4;

    uint64_t acc2[4][2];
#pragma unroll
    for (int i = 0; i < 4; i++) { acc2[i][0] = 0ull; acc2[i][1] = 0ull; }
    float sa0 = 0.f, sa1 = 0.f, sa2 = 0.f, sa3 = 0.f;

#pragma unroll 4
    for (int i = 0; i < 128; i++) {
        int nn = g * 128 + i;
        const float4 a = *(const float4*)&ekT[nn * 36 + d0];
        const ulonglong2 bv = *(const ulonglong2*)&vT[nn * 36 + e0];
        const float av[4] = {a.x, a.y, a.z, a.w};
#pragma unroll
        for (int ii = 0; ii < 4; ii++) {
            const uint64_t ad = pack_dup(av[ii]);
            ffma2(acc2[ii][0], ad, bv.x);
            ffma2(acc2[ii][1], ad, bv.y);
        }
        if (te == 0) { sa0 += a.x; sa1 += a.y; sa2 += a.z; sa3 += a.w; }
    }
    __syncthreads();

    // reduce the 4 group-partials through smem (reuse)
    float* sbuf  = sm;                   // [4][1024]
    float* sbufS = sm + 4096;            // [4][32]
#pragma unroll
    for (int ii = 0; ii < 4; ii++) {
        float2 f0 = unpk(acc2[ii][0]), f1 = unpk(acc2[ii][1]);
        float* r = &sbuf[g * 1024 + (d0 + ii) * 32 + e0];
        r[0] = f0.x; r[1] = f0.y; r[2] = f1.x; r[3] = f1.y;
    }
    if (te == 0) {
        sbufS[g * 32 + d0 + 0] = sa0; sbufS[g * 32 + d0 + 1] = sa1;
        sbufS[g * 32 + d0 + 2] = sa2; sbufS[g * 32 + d0 + 3] = sa3;
    }
    __syncthreads();

    const size_t pbase = ((size_t)bh * 32 + chunk) * 1056;
    for (int idx = tid; idx < 1024; idx += 256)
        g_part[pbase + idx] = sbuf[idx] + sbuf[1024 + idx] + sbuf[2048 + idx] + sbuf[3072 + idx];
    if (tid < 32)
        g_part[pbase + 1024 + tid] = sbufS[tid] + sbufS[32 + tid] + sbufS[64 + tid] + sbufS[96 + tid];
}

// =============================================================================
// K2b: per b: reduce 32 chunk-partials, normalize by sumexp, build fused
//      W2[ch=h*32+d][c] = sum_e w_out[c][h*32+e] * ctx[h][d][e] / S[h][d]
// =============================================================================
__global__ __launch_bounds__(256, 1)
void k_ctx_fin(const float* __restrict__ w_out)
{
    extern __shared__ float sm[];
    float* ctxs = sm;            // [h][d][e]
    float* Ss   = sm + 4096;     // 1/sumexp per (h,d)
    float* ws2  = sm + 4224;     // [ch2][c] stride 132

    const int b = blockIdx.x;
    const int tid = threadIdx.x;

    for (int lin = tid; lin < 16384; lin += 256) {
        int c = lin >> 7, ch2 = lin & 127;
        ws2[ch2 * 132 + c] = w_out[c * NCH + ch2];
    }

    for (int h = 0; h < 4; h++) {
        const size_t pb = (size_t)(b * 4 + h) * 32 * 1056;
        for (int idx = tid; idx < 1024; idx += 256) {
            float s = 0.f;
#pragma unroll
            for (int ch = 0; ch < 32; ch++) s += g_part[pb + (size_t)ch * 1056 + idx];
            ctxs[h * 1024 + idx] = s;
        }
    }
    if (tid < 128) {
        int h = tid >> 5, d = tid & 31;
        const size_t pb = (size_t)(b * 4 + h) * 32 * 1056 + 1024;
        float s = 0.f;
#pragma unroll
        for (int ch = 0; ch < 32; ch++) s += g_part[pb + (size_t)ch * 1056 + d];
        Ss[tid] = 1.0f / s;
    }
    __syncthreads();

    for (int oidx = tid; oidx < 16384; oidx += 256) {
        int ch = oidx >> 7, c = oidx & 127;     // lanes: consecutive c (bank-clean)
        int h = ch >> 5, d = ch & 31;
        const float* cr = &ctxs[h * 1024 + d * 32];
        float acc = 0.f;
#pragma unroll
        for (int e = 0; e < 32; e++)
            acc = fmaf(ws2[(h * 32 + e) * 132 + c], cr[e], acc);
        g_W2T[(size_t)b * 16384 + ch * NCH + c] = acc * Ss[ch];
    }
}

// =============================================================================
// K3: y = W2_b @ q + b_out, then LayerNorm over C.  128 positions / block.
// 8x8 register tile via fma.rn.f32x2; LN stats via register partial reduction.
// smem: qs[128][128] | W2s[128][132] | red[2][2048] | mean/rstd = 150,528 B
// =============================================================================
__global__ __launch_bounds__(256, 1)
void k_out(const float* __restrict__ b_out, const float* __restrict__ ln_g,
           const float* __restrict__ ln_b, float* __restrict__ out)
{
    extern __shared__ float sm[];
    float* qs     = sm;            // [ch][p] stride 128
    float* W2s    = sm + 16384;    // [ch][c] stride 132
    float* red    = W2s + 16896;   // [2][16][128]
    float* mean_s = red + 4096;    // [128]
    float* rstd_s = mean_s + 128;  // [128]

    const int b   = blockIdx.x >> 7;
    const int n0  = (blockIdx.x & 127) << 7;
    const int tid = threadIdx.x;

    const float* qg = g_q + (size_t)b * NCH * NPOS + n0;
#pragma unroll
    for (int i = 0; i < 16; i++) {
        int lin = tid + i * 256;
        int ch = lin >> 5, pv = lin & 31;
        ((float4*)qs)[ch * 32 + pv] = ((const float4*)(qg + (size_t)ch * NPOS))[pv];
    }
#pragma unroll
    for (int i = 0; i < 64; i++) {
        int lin = tid + i * 256;          // 16384
        int ch = lin >> 7, cl = lin & 127;
        W2s[ch * 132 + cl] = g_W2T[(size_t)b * 16384 + lin];
    }
    __syncthreads();

    const int to = tid >> 4, tp = tid & 15;
    const int c0 = to * 8, p0 = tp * 8;

    uint64_t acc2[8][4];
#pragma unroll
    for (int i = 0; i < 8; i++)
#pragma unroll
        for (int j = 0; j < 4; j++) acc2[i][j] = 0ull;

#pragma unroll 2
    for (int ch = 0; ch < 128; ch++) {
        const ulonglong2 xa = *(const ulonglong2*)&qs[ch * 128 + p0];
        const ulonglong2 xc = *(const ulonglong2*)&qs[ch * 128 + p0 + 4];
        const uint64_t xp[4] = {xa.x, xa.y, xc.x, xc.y};
        const float4 w0 = *(const float4*)&W2s[ch * 132 + c0];
        const float4 w1 = *(const float4*)&W2s[ch * 132 + c0 + 4];
        const float wv[8] = {w0.x, w0.y, w0.z, w0.w, w1.x, w1.y, w1.z, w1.w};
#pragma unroll
        for (int i = 0; i < 8; i++) {
            const uint64_t wd = pack_dup(wv[i]);
#pragma unroll
            for (int j = 0; j < 4; j++) ffma2(acc2[i][j], wd, xp[j]);
        }
    }

    // unpack, add bias, per-thread partial sums over the 8 local channels
    float acc[8][8];
#pragma unroll
    for (int i = 0; i < 8; i++) {
        const float bo = b_out[c0 + i];
        float2 f0 = unpk(acc2[i][0]), f1 = unpk(acc2[i][1]);
        float2 f2 = unpk(acc2[i][2]), f3 = unpk(acc2[i][3]);
        acc[i][0] = f0.x + bo; acc[i][1] = f0.y + bo;
        acc[i][2] = f1.x + bo; acc[i][3] = f1.y + bo;
        acc[i][4] = f2.x + bo; acc[i][5] = f2.y + bo;
        acc[i][6] = f3.x + bo; acc[i][7] = f3.y + bo;
    }
#pragma unroll
    for (int j = 0; j < 8; j++) {
        float s = 0.f, s2 = 0.f;
#pragma unroll
        for (int i = 0; i < 8; i++) {
            s += acc[i][j];
            s2 = fmaf(acc[i][j], acc[i][j], s2);
        }
        red[to * 128 + p0 + j]        = s;
        red[2048 + to * 128 + p0 + j] = s2;
    }
    __syncthreads();

    if (tid < 128) {
        const int p = tid;
        float s = 0.f, s2 = 0.f;
#pragma unroll
        for (int t = 0; t < 16; t++) {
            s  += red[t * 128 + p];
            s2 += red[2048 + t * 128 + p];
        }
        const float mu  = s * (1.0f / 128.0f);
        const float var = s2 * (1.0f / 128.0f) - mu * mu;
        mean_s[p] = mu;
        rstd_s[p] = rsqrtf(var + 1e-5f);
    }
    __syncthreads();

    float mu[8], rs[8];
#pragma unroll
    for (int j = 0; j < 8; j++) { mu[j] = mean_s[p0 + j]; rs[j] = rstd_s[p0 + j]; }

    float* ob = out + ((size_t)b * NCH + c0) * NPOS + n0 + p0;
#pragma unroll
    for (int i = 0; i < 8; i++) {
        const float gg = ln_g[c0 + i], bb = ln_b[c0 + i];
        float v[8];
#pragma unroll
        for (int j = 0; j < 8; j++)
            v[j] = (acc[i][j] - mu[j]) * rs[j] * gg + bb;
        *(float4*)(ob + (size_t)i * NPOS)     = make_float4(v[0], v[1], v[2], v[3]);
        *(float4*)(ob + (size_t)i * NPOS + 4) = make_float4(v[4], v[5], v[6], v[7]);
    }
}

// =============================================================================
extern "C" void kernel_launch(void* const* d_in, const int* in_sizes, int n_in,
                              void* d_out, int out_size)
{
    const float* x     = (const float*)d_in[0];
    const float* w_qkv = (const float*)d_in[1];
    const float* w_out = (const float*)d_in[2];
    const float* b_out = (const float*)d_in[3];
    const float* ln_g  = (const float*)d_in[4];
    const float* ln_b  = (const float*)d_in[5];
    float* out = (float*)d_out;

    cudaFuncSetAttribute(k_qkv,      cudaFuncAttributeMaxDynamicSharedMemorySize, 200704);
    cudaFuncSetAttribute(k_ctx_part, cudaFuncAttributeMaxDynamicSharedMemorySize, 147456);
    cudaFuncSetAttribute(k_ctx_fin,  cudaFuncAttributeMaxDynamicSharedMemorySize,  84480);
    cudaFuncSetAttribute(k_out,      cudaFuncAttributeMaxDynamicSharedMemorySize, 150528);

    k_qkv<<<2048, 256, 200704>>>(x, w_qkv);
    k_ctx_part<<<2048, 256, 147456>>>();
    k_ctx_fin<<<16, 256, 84480>>>(w_out);
    k_out<<<2048, 256, 150528>>>(b_out, ln_g, ln_b, out);
}

// round 5
// speedup vs baseline: 1.6990x; 1.6990x over previous
#include <cuda_runtime.h>
#include <cuda_bf16.h>
#include <math.h>
#include <stdint.h>

#define NPOS 16384          // H*W
#define NB   16             // batch
#define NCH  128            // C == hidden
#define NCHUNK 32           // context n-chunks (512 each)

// ---------------- device scratch (allocation-free rule: __device__ globals) ----
__device__ uint32_t g_qhi[NB * NPOS * 64];       // q bf16-hi pairs   [b][n][ch/2]
__device__ uint32_t g_qlo[NB * NPOS * 64];       // q bf16-lo pairs   [b][n][ch/2]
__device__ float    g_kT [NB * NPOS * NCH];      // raw k f32         [b][n][ch]
__device__ float    g_vT [NB * NPOS * NCH];      // raw v f32         [b][n][ch]
__device__ float    g_part[NB * 4 * NCHUNK * 1056];
__device__ uint32_t g_W2hi[NB * NCH * 64];       // fused W2 bf16-hi  [b][c][ch/2]
__device__ uint32_t g_W2lo[NB * NCH * 64];       // fused W2 bf16-lo  [b][c][ch/2]

// ---------------- helpers -------------------------------------------------------
__device__ __forceinline__ uint32_t smem_u32(const void* p) {
    uint32_t a;
    asm("{ .reg .u64 t; cvta.to.shared.u64 t, %1; cvt.u32.u64 %0, t; }" : "=r"(a) : "l"(p));
    return a;
}
// swizzled byte offset within a 128x128 bf16 tile (256B rows, XOR on 16B chunks)
__device__ __forceinline__ uint32_t toff(int r, int c) {
    return (uint32_t)(r * 256 + (((c >> 3) ^ (r & 7)) << 4) + ((c & 7) << 1));
}
__device__ __forceinline__ void ldsm4(uint32_t* r, uint32_t a) {
    asm volatile("ldmatrix.sync.aligned.m8n8.x4.shared.b16 {%0,%1,%2,%3}, [%4];"
                 : "=r"(r[0]), "=r"(r[1]), "=r"(r[2]), "=r"(r[3]) : "r"(a));
}
__device__ __forceinline__ void ldsm4t(uint32_t* r, uint32_t a) {
    asm volatile("ldmatrix.sync.aligned.m8n8.x4.trans.shared.b16 {%0,%1,%2,%3}, [%4];"
                 : "=r"(r[0]), "=r"(r[1]), "=r"(r[2]), "=r"(r[3]) : "r"(a));
}
__device__ __forceinline__ void mma16816(float* d, const uint32_t* a, uint32_t b0, uint32_t b1) {
    asm volatile(
        "mma.sync.aligned.m16n8k16.row.col.f32.bf16.bf16.f32 "
        "{%0,%1,%2,%3}, {%4,%5,%6,%7}, {%8,%9}, {%0,%1,%2,%3};"
        : "+f"(d[0]), "+f"(d[1]), "+f"(d[2]), "+f"(d[3])
        : "r"(a[0]), "r"(a[1]), "r"(a[2]), "r"(a[3]), "r"(b0), "r"(b1));
}

// 128x128x128 warp-tiled GEMM pass. acc[2][8][4] = 32(m) x 64(n) per warp.
// A tile: ATRANS ? storage [k][m] (use ldmatrix.trans) : storage [m][k].
// B tile: storage [n][k].
template<bool ATRANS>
__device__ __forceinline__ void gemm128(float (&acc)[2][8][4], uint32_t aB, uint32_t bB,
                                        int wm, int wn, int lane)
{
    const int l7  = lane & 7;
    const int lb3 = (lane >> 3) & 1;
    const int lb4 = (lane >> 4) & 1;
#pragma unroll
    for (int k = 0; k < 8; k++) {
        uint32_t a[2][4];
#pragma unroll
        for (int t = 0; t < 2; t++) {
            uint32_t addr;
            if (ATRANS)
                addr = aB + toff(k * 16 + l7 + lb4 * 8, wm * 32 + t * 16 + lb3 * 8);
            else
                addr = aB + toff(wm * 32 + t * 16 + l7 + lb3 * 8, k * 16 + lb4 * 8);
            if (ATRANS) ldsm4t(a[t], addr); else ldsm4(a[t], addr);
        }
        uint32_t bf[4][4];
#pragma unroll
        for (int u2 = 0; u2 < 4; u2++)
            ldsm4(bf[u2], bB + toff(wn * 64 + u2 * 16 + l7 + lb4 * 8, k * 16 + lb3 * 8));
#pragma unroll
        for (int t = 0; t < 2; t++)
#pragma unroll
            for (int u = 0; u < 8; u++)
                mma16816(acc[t][u], a[t], bf[u >> 1][(u & 1) * 2], bf[u >> 1][(u & 1) * 2 + 1]);
    }
}

// load a 128x128 f32 tile (row stride strideF) into split bf16 hi/lo swizzled tiles
__device__ __forceinline__ void load_split(char* smc, int hiOff, int loOff,
                                           const float* __restrict__ src,
                                           int strideF, int tid)
{
#pragma unroll
    for (int i = 0; i < 16; i++) {
        int lin = tid + i * 256;
        int r = lin >> 5, cq = lin & 31;
        float4 v = *(const float4*)(src + (size_t)r * strideF + cq * 4);
        __nv_bfloat162 h01 = __float22bfloat162_rn(make_float2(v.x, v.y));
        __nv_bfloat162 h23 = __float22bfloat162_rn(make_float2(v.z, v.w));
        float2 hf01 = __bfloat1622float2(h01), hf23 = __bfloat1622float2(h23);
        __nv_bfloat162 l01 = __float22bfloat162_rn(make_float2(v.x - hf01.x, v.y - hf01.y));
        __nv_bfloat162 l23 = __float22bfloat162_rn(make_float2(v.z - hf23.x, v.w - hf23.y));
        uint32_t o = toff(r, cq * 4);
        *(uint32_t*)(smc + hiOff + o)     = *(uint32_t*)&h01;
        *(uint32_t*)(smc + hiOff + o + 4) = *(uint32_t*)&h23;
        *(uint32_t*)(smc + loOff + o)     = *(uint32_t*)&l01;
        *(uint32_t*)(smc + loOff + o + 4) = *(uint32_t*)&l23;
    }
}

// =============================================================================
// K1: qkv = w_qkv @ x via mma.sync bf16-split.  M=128 positions, 3 chunks of
// 128 out-channels.  Fused q-softmax (lane-local shuffles).
// smem: xs hi/lo 64K | ws hi/lo 64K = 131072 B
// =============================================================================
#define K1_XHI 0
#define K1_XLO 32768
#define K1_WHI 65536
#define K1_WLO 98304

__global__ __launch_bounds__(256, 1)
void k_qkv(const float* __restrict__ x, const float* __restrict__ w_qkv)
{
    extern __shared__ char smc[];
    const uint32_t sb = smem_u32(smc);
    const int tid = threadIdx.x;
    const int warp = tid >> 5, lane = tid & 31;
    const int wm = warp & 3, wn = warp >> 2;

    const int b  = blockIdx.x >> 7;
    const int n0 = (blockIdx.x & 127) << 7;

    // A = x^T: store x tile as [c][p] (k-major rows = c); trans-ldmatrix later
    load_split(smc, K1_XHI, K1_XLO, x + (size_t)b * NCH * NPOS + n0, NPOS, tid);
    // B = w chunk0: [o][c]
    load_split(smc, K1_WHI, K1_WLO, w_qkv, NCH, tid);
    __syncthreads();

    for (int chunk = 0; chunk < 3; chunk++) {
        float acc[2][8][4];
#pragma unroll
        for (int t = 0; t < 2; t++)
#pragma unroll
            for (int u = 0; u < 8; u++)
#pragma unroll
                for (int r = 0; r < 4; r++) acc[t][u][r] = 0.f;

        gemm128<true>(acc, sb + K1_XHI, sb + K1_WHI, wm, wn, lane);
        gemm128<true>(acc, sb + K1_XHI, sb + K1_WLO, wm, wn, lane);
        gemm128<true>(acc, sb + K1_XLO, sb + K1_WHI, wm, wn, lane);

        if (chunk == 0) {
            // q: softmax over 32 channels per head (head = 32 cols; warp holds 2 heads)
            const float scale = 0.17677669529663687f; // 32^-0.5
#pragma unroll
            for (int t = 0; t < 2; t++)
#pragma unroll
            for (int rh = 0; rh < 2; rh++) {
                float e[8][2];
                float sA = 0.f, sB = 0.f;
#pragma unroll
                for (int u = 0; u < 8; u++)
#pragma unroll
                    for (int j = 0; j < 2; j++) {
                        float v = __expf(acc[t][u][rh * 2 + j]);
                        e[u][j] = v;
                        if (u < 4) sA += v; else sB += v;
                    }
                sA += __shfl_xor_sync(0xffffffffu, sA, 1);
                sA += __shfl_xor_sync(0xffffffffu, sA, 2);
                sB += __shfl_xor_sync(0xffffffffu, sB, 1);
                sB += __shfl_xor_sync(0xffffffffu, sB, 2);
                const float invA = scale / sA, invB = scale / sB;
                const int p = wm * 32 + t * 16 + rh * 8 + (lane >> 2);
                const size_t rowb = ((size_t)b * NPOS + n0 + p) * 64;
#pragma unroll
                for (int u = 0; u < 8; u++) {
                    float inv = (u < 4) ? invA : invB;
                    float v0 = e[u][0] * inv, v1 = e[u][1] * inv;
                    __nv_bfloat162 h = __float22bfloat162_rn(make_float2(v0, v1));
                    float2 hf = __bfloat1622float2(h);
                    __nv_bfloat162 lo = __float22bfloat162_rn(make_float2(v0 - hf.x, v1 - hf.y));
                    int cp = wn * 32 + u * 4 + (lane & 3);
                    g_qhi[rowb + cp] = *(uint32_t*)&h;
                    g_qlo[rowb + cp] = *(uint32_t*)&lo;
                }
            }
        } else {
            float* gdst = (chunk == 1) ? g_kT : g_vT;
#pragma unroll
            for (int t = 0; t < 2; t++)
#pragma unroll
            for (int rh = 0; rh < 2; rh++) {
                const int p = wm * 32 + t * 16 + rh * 8 + (lane >> 2);
                float* rowp = gdst + ((size_t)b * NPOS + n0 + p) * 128 + wn * 64 + (lane & 3) * 2;
#pragma unroll
                for (int u = 0; u < 8; u++)
                    *(float2*)(rowp + u * 8) = make_float2(acc[t][u][rh * 2], acc[t][u][rh * 2 + 1]);
            }
        }

        __syncthreads();
        if (chunk < 2) {
            load_split(smc, K1_WHI, K1_WLO, w_qkv + (size_t)(chunk + 1) * 128 * NCH, NCH, tid);
            __syncthreads();
        }
    }
}

// =============================================================================
// K2a: per (b,h,chunk of 512 n): partial ctx[d][e] = sum exp(k[n,d]) v[n,e]
//      reads g_kT/g_vT [b][n][128].  smem 147,456 B
// =============================================================================
__device__ __forceinline__ void ffma2(uint64_t& acc, uint64_t a, uint64_t b) {
    asm("fma.rn.f32x2 %0, %1, %2, %0;" : "+l"(acc) : "l"(a), "l"(b));
}
__device__ __forceinline__ uint64_t pack_dup(float w) {
    uint64_t r;
    asm("mov.b64 %0, {%1, %1};" : "=l"(r) : "f"(w));
    return r;
}
__device__ __forceinline__ float2 unpk(uint64_t v) {
    float2 f;
    asm("mov.b64 {%0, %1}, %2;" : "=f"(f.x), "=f"(f.y) : "l"(v));
    return f;
}

__global__ __launch_bounds__(256, 1)
void k_ctx_part()
{
    extern __shared__ float sm[];
    float* ekT = sm;            // [nn][d] stride 36
    float* vT  = sm + 18432;

    const int chunk = blockIdx.x & 31;
    const int bh    = blockIdx.x >> 5;   // b*4 + h
    const int b = bh >> 2, h = bh & 3;
    const int tid   = threadIdx.x;
    const size_t rowbase = (size_t)b * NPOS + (size_t)chunk * 512;

    for (int i = 0; i < 64; i++) {
        int lin = tid + i * 256;         // 16384 = 512 nn x 32 d
        int nn = lin >> 5, d = lin & 31;
        ekT[nn * 36 + d] = __expf(g_kT[(rowbase + nn) * NCH + h * 32 + d]);
        vT [nn * 36 + d] =        g_vT[(rowbase + nn) * NCH + h * 32 + d];
    }
    __syncthreads();

    const int g  = tid >> 6;
    const int t  = tid & 63;
    const int td = t >> 3, te = t & 7;
    const int d0 = td * 4, e0 = te * 4;

    uint64_t acc2[4][2];
#pragma unroll
    for (int i = 0; i < 4; i++) { acc2[i][0] = 0ull; acc2[i][1] = 0ull; }
    float sa0 = 0.f, sa1 = 0.f, sa2 = 0.f, sa3 = 0.f;

#pragma unroll 4
    for (int i = 0; i < 128; i++) {
        int nn = g * 128 + i;
        const float4 a = *(const float4*)&ekT[nn * 36 + d0];
        const ulonglong2 bv = *(const ulonglong2*)&vT[nn * 36 + e0];
        const float av[4] = {a.x, a.y, a.z, a.w};
#pragma unroll
        for (int ii = 0; ii < 4; ii++) {
            const uint64_t ad = pack_dup(av[ii]);
            ffma2(acc2[ii][0], ad, bv.x);
            ffma2(acc2[ii][1], ad, bv.y);
        }
        if (te == 0) { sa0 += a.x; sa1 += a.y; sa2 += a.z; sa3 += a.w; }
    }
    __syncthreads();

    float* sbuf  = sm;                   // [4][1024]
    float* sbufS = sm + 4096;            // [4][32]
#pragma unroll
    for (int ii = 0; ii < 4; ii++) {
        float2 f0 = unpk(acc2[ii][0]), f1 = unpk(acc2[ii][1]);
        float* r = &sbuf[g * 1024 + (d0 + ii) * 32 + e0];
        r[0] = f0.x; r[1] = f0.y; r[2] = f1.x; r[3] = f1.y;
    }
    if (te == 0) {
        sbufS[g * 32 + d0 + 0] = sa0; sbufS[g * 32 + d0 + 1] = sa1;
        sbufS[g * 32 + d0 + 2] = sa2; sbufS[g * 32 + d0 + 3] = sa3;
    }
    __syncthreads();

    const size_t pbase = ((size_t)bh * 32 + chunk) * 1056;
    for (int idx = tid; idx < 1024; idx += 256)
        g_part[pbase + idx] = sbuf[idx] + sbuf[1024 + idx] + sbuf[2048 + idx] + sbuf[3072 + idx];
    if (tid < 32)
        g_part[pbase + 1024 + tid] = sbufS[tid] + sbufS[32 + tid] + sbufS[64 + tid] + sbufS[96 + tid];
}

// =============================================================================
// K2b: reduce chunk partials, normalize, emit fused W2 as packed bf16 hi/lo
//      [b][c][ch/2].  smem: ctxs 4224 | Ss 128 | ws2 16384 = 82,944 B
// =============================================================================
__global__ __launch_bounds__(256, 1)
void k_ctx_fin(const float* __restrict__ w_out)
{
    extern __shared__ float sm[];
    float* ctxs = sm;            // [h][d][33]
    float* Ss   = sm + 4224;
    float* ws2  = sm + 4352;     // [c][ch] copy of w_out

    const int b = blockIdx.x;
    const int tid = threadIdx.x;

    for (int lin = tid; lin < 16384; lin += 256) ws2[lin] = w_out[lin];

    for (int h = 0; h < 4; h++) {
        const size_t pb = (size_t)(b * 4 + h) * 32 * 1056;
        for (int idx = tid; idx < 1024; idx += 256) {
            float s = 0.f;
#pragma unroll
            for (int ch = 0; ch < 32; ch++) s += g_part[pb + (size_t)ch * 1056 + idx];
            ctxs[h * 1056 + (idx >> 5) * 33 + (idx & 31)] = s;
        }
    }
    if (tid < 128) {
        int h = tid >> 5, d = tid & 31;
        const size_t pb = (size_t)(b * 4 + h) * 32 * 1056 + 1024;
        float s = 0.f;
#pragma unroll
        for (int ch = 0; ch < 32; ch++) s += g_part[pb + (size_t)ch * 1056 + d];
        Ss[tid] = 1.0f / s;
    }
    __syncthreads();

    for (int oidx = tid; oidx < 8192; oidx += 256) {
        int c = oidx >> 6, cp = oidx & 63;
        int ch0 = cp * 2;
        int h = ch0 >> 5, d = ch0 & 31;
        const float* cr0 = &ctxs[h * 1056 + d * 33];
        const float* cr1 = cr0 + 33;
        const float* wr  = &ws2[c * 128 + h * 32];
        float a0 = 0.f, a1 = 0.f;
#pragma unroll
        for (int e = 0; e < 32; e++) {
            a0 = fmaf(wr[e], cr0[e], a0);
            a1 = fmaf(wr[e], cr1[e], a1);
        }
        float v0 = a0 * Ss[ch0], v1 = a1 * Ss[ch0 + 1];
        __nv_bfloat162 hp = __float22bfloat162_rn(make_float2(v0, v1));
        float2 hf = __bfloat1622float2(hp);
        __nv_bfloat162 lp = __float22bfloat162_rn(make_float2(v0 - hf.x, v1 - hf.y));
        g_W2hi[(size_t)b * 8192 + oidx] = *(uint32_t*)&hp;
        g_W2lo[(size_t)b * 8192 + oidx] = *(uint32_t*)&lp;
    }
}

// =============================================================================
// K3: y = W2_b @ q + b_out via mma.sync bf16-split, LayerNorm over C fused.
// M = 128 out-channels (coalesced writes), N = 128 positions.
// smem: q hi/lo 64K | W2 hi/lo 64K | red 4K | stats 1K = 136,192 B
// =============================================================================
#define K3_QHI 0
#define K3_QLO 32768
#define K3_WHI 65536
#define K3_WLO 98304
#define K3_RS  131072
#define K3_RQ  133120
#define K3_MU  135168
#define K3_RST 135680

__global__ __launch_bounds__(256, 1)
void k_out(const float* __restrict__ b_out, const float* __restrict__ ln_g,
           const float* __restrict__ ln_b, float* __restrict__ out)
{
    extern __shared__ char smc[];
    const uint32_t sb = smem_u32(smc);
    float* red_s = (float*)(smc + K3_RS);    // [4][128]
    float* red_q = (float*)(smc + K3_RQ);    // [4][128]
    float* mu_s  = (float*)(smc + K3_MU);    // [128]
    float* rs_s  = (float*)(smc + K3_RST);   // [128]

    const int tid = threadIdx.x;
    const int warp = tid >> 5, lane = tid & 31;
    const int wm = warp & 3, wn = warp >> 2;
    const int b  = blockIdx.x >> 7;
    const int n0 = (blockIdx.x & 127) << 7;

    // load q tiles [p][ch] (bf16 pairs already) and W2 tiles [c][ch]
#pragma unroll
    for (int i = 0; i < 32; i++) {
        int it = tid + i * 256;              // 8192
        int r = it >> 6, cp = it & 63;
        uint32_t o = toff(r, cp * 2);
        *(uint32_t*)(smc + K3_QHI + o) = g_qhi[((size_t)b * NPOS + n0 + r) * 64 + cp];
        *(uint32_t*)(smc + K3_QLO + o) = g_qlo[((size_t)b * NPOS + n0 + r) * 64 + cp];
        *(uint32_t*)(smc + K3_WHI + o) = g_W2hi[(size_t)b * 8192 + it];
        *(uint32_t*)(smc + K3_WLO + o) = g_W2lo[(size_t)b * 8192 + it];
    }
    __syncthreads();

    float acc[2][8][4];
#pragma unroll
    for (int t = 0; t < 2; t++)
#pragma unroll
        for (int u = 0; u < 8; u++)
#pragma unroll
            for (int r = 0; r < 4; r++) acc[t][u][r] = 0.f;

    gemm128<false>(acc, sb + K3_WHI, sb + K3_QHI, wm, wn, lane);
    gemm128<false>(acc, sb + K3_WHI, sb + K3_QLO, wm, wn, lane);
    gemm128<false>(acc, sb + K3_WLO, sb + K3_QHI, wm, wn, lane);

    // bias (rows = out-channel c)
#pragma unroll
    for (int t = 0; t < 2; t++)
#pragma unroll
        for (int h = 0; h < 2; h++) {
            const float bo = b_out[wm * 32 + t * 16 + h * 8 + (lane >> 2)];
#pragma unroll
            for (int u = 0; u < 8; u++) {
                acc[t][u][h * 2]     += bo;
                acc[t][u][h * 2 + 1] += bo;
            }
        }

    // LN partials: per column, sum over this warp's 32 rows via shfl 4/8/16
#pragma unroll
    for (int u = 0; u < 8; u++)
#pragma unroll
        for (int j = 0; j < 2; j++) {
            float a0 = acc[0][u][j],     a1 = acc[0][u][2 + j];
            float a2 = acc[1][u][j],     a3 = acc[1][u][2 + j];
            float s = a0 + a1 + a2 + a3;
            float q = a0 * a0 + a1 * a1 + a2 * a2 + a3 * a3;
            s += __shfl_xor_sync(0xffffffffu, s, 4);
            q += __shfl_xor_sync(0xffffffffu, q, 4);
            s += __shfl_xor_sync(0xffffffffu, s, 8);
            q += __shfl_xor_sync(0xffffffffu, q, 8);
            s += __shfl_xor_sync(0xffffffffu, s, 16);
            q += __shfl_xor_sync(0xffffffffu, q, 16);
            if ((lane >> 2) == 0) {
                int col = wn * 64 + u * 8 + (lane & 3) * 2 + j;
                red_s[wm * 128 + col] = s;
                red_q[wm * 128 + col] = q;
            }
        }
    __syncthreads();

    if (tid < 128) {
        float s = red_s[tid] + red_s[128 + tid] + red_s[256 + tid] + red_s[384 + tid];
        float q = red_q[tid] + red_q[128 + tid] + red_q[256 + tid] + red_q[384 + tid];
        float mu  = s * (1.0f / 128.0f);
        float var = q * (1.0f / 128.0f) - mu * mu;
        mu_s[tid] = mu;
        rs_s[tid] = rsqrtf(var + 1e-5f);
    }
    __syncthreads();

    // normalize + write (rows c contiguous along positions -> coalesced v2)
#pragma unroll
    for (int t = 0; t < 2; t++)
#pragma unroll
        for (int h = 0; h < 2; h++) {
            const int c = wm * 32 + t * 16 + h * 8 + (lane >> 2);
            const float g  = ln_g[c];
            const float bb = ln_b[c];
            float* rowp = out + ((size_t)b * NCH + c) * NPOS + n0 + wn * 64 + (lane & 3) * 2;
#pragma unroll
            for (int u = 0; u < 8; u++) {
                int col = wn * 64 + u * 8 + (lane & 3) * 2;
                float2 mu2 = *(float2*)&mu_s[col];
                float2 rs2 = *(float2*)&rs_s[col];
                float v0 = (acc[t][u][h * 2]     - mu2.x) * rs2.x * g + bb;
                float v1 = (acc[t][u][h * 2 + 1] - mu2.y) * rs2.y * g + bb;
                *(float2*)(rowp + u * 8) = make_float2(v0, v1);
            }
        }
}

// =============================================================================
extern "C" void kernel_launch(void* const* d_in, const int* in_sizes, int n_in,
                              void* d_out, int out_size)
{
    const float* x     = (const float*)d_in[0];
    const float* w_qkv = (const float*)d_in[1];
    const float* w_out = (const float*)d_in[2];
    const float* b_out = (const float*)d_in[3];
    const float* ln_g  = (const float*)d_in[4];
    const float* ln_b  = (const float*)d_in[5];
    float* out = (float*)d_out;

    cudaFuncSetAttribute(k_qkv,      cudaFuncAttributeMaxDynamicSharedMemorySize, 131072);
    cudaFuncSetAttribute(k_ctx_part, cudaFuncAttributeMaxDynamicSharedMemorySize, 147456);
    cudaFuncSetAttribute(k_ctx_fin,  cudaFuncAttributeMaxDynamicSharedMemorySize,  82944);
    cudaFuncSetAttribute(k_out,      cudaFuncAttributeMaxDynamicSharedMemorySize, 136192);

    k_qkv<<<2048, 256, 131072>>>(x, w_qkv);
    k_ctx_part<<<2048, 256, 147456>>>();
    k_ctx_fin<<<16, 256, 82944>>>(w_out);
    k_out<<<2048, 256, 136192>>>(b_out, ln_g, ln_b, out);
}